// round 10
// baseline (speedup 1.0000x reference)
#include <cuda_runtime.h>
#include <cstdint>

#define N_PIX 4096
#define DIMC  256
#define HID   512
#define EPSB  1e-5f

// scratch (no cudaMalloc allowed)
__device__ float    g_qkv[2 * HID * N_PIX];       // 16 MB
__device__ float    g_y[2 * DIMC * N_PIX];        //  8 MB
__device__ uint32_t g_qt[8 * N_PIX * 32];         //  4 MB  (tf32, [bh][i][d-perm], scale*log2e folded)
__device__ uint32_t g_kt[8 * N_PIX * 32];         //  4 MB  (tf32, [bh][j][d-perm])
__device__ uint32_t g_vt[8 * 64 * N_PIX];         //  8 MB  (tf32, [bh][d][j-perm])

__device__ __forceinline__ uint32_t f2tf(float f) {
    uint32_t r; asm("cvt.rna.tf32.f32 %0, %1;" : "=r"(r) : "f"(f)); return r;
}
// pair-permute within 8-groups: k -> (k&3)*2 + (k>>2), so (q4, q4+4) adjacent
__device__ __forceinline__ int kperm(int k) {
    return (k & ~7) | ((k & 3) << 1) | ((k >> 2) & 1);
}
// C[m16][n8] += A[m16][k8](row) * B[k8][n8](col), tf32 in, f32 accum
__device__ __forceinline__ void mma8(float* c, const uint32_t* a, const uint32_t* b) {
    asm volatile("mma.sync.aligned.m16n8k8.row.col.f32.tf32.tf32.f32 "
        "{%0,%1,%2,%3}, {%4,%5,%6,%7}, {%8,%9}, {%0,%1,%2,%3};"
        : "+f"(c[0]), "+f"(c[1]), "+f"(c[2]), "+f"(c[3])
        : "r"(a[0]), "r"(a[1]), "r"(a[2]), "r"(a[3]), "r"(b[0]), "r"(b[1]));
}

// ---------------------------------------------------------------------------
// Tensor-core GEMM + folded BN. BM=64, BN=128, BK=32, 256 thr (8 warps 2x4).
// ---------------------------------------------------------------------------
__global__ void __launch_bounds__(256)
gemm_tc(const float* __restrict__ W, const float* __restrict__ X,
        const float* __restrict__ gg, const float* __restrict__ bb,
        const float* __restrict__ mm, const float* __restrict__ vv,
        float* __restrict__ out, int M)
{
    __shared__ uint32_t Ws[64 * 36];
    __shared__ uint32_t Xs[32 * 136];
    const float* Xb = X + (size_t)blockIdx.z * DIMC * N_PIX;
    float* outb = out + (size_t)blockIdx.z * M * N_PIX;
    const int m0 = blockIdx.y * 64, n0 = blockIdx.x * 128;
    const int tid = threadIdx.x;
    const int w = tid >> 5, lane = tid & 31;
    const int gid = lane >> 2, q4 = lane & 3;
    const int wr = w >> 2, wc = w & 3;

    float acc[2][4][4] = {};

    for (int k0 = 0; k0 < DIMC; k0 += 32) {
        #pragma unroll
        for (int r = 0; r < 2; r++) {
            int f = r * 256 + tid;
            int m = f >> 3, k4 = (f & 7) * 4;
            float4 wv = *(const float4*)(W + (size_t)(m0 + m) * DIMC + k0 + k4);
            uint2 lo = make_uint2(f2tf(wv.x), f2tf(wv.y));
            uint2 hi = make_uint2(f2tf(wv.z), f2tf(wv.w));
            *(uint2*)(Ws + m * 36 + k4)     = lo;
            *(uint2*)(Ws + m * 36 + k4 + 2) = hi;
        }
        #pragma unroll
        for (int r = 0; r < 4; r++) {
            int f = r * 256 + tid;
            int k = f >> 5, n4 = (f & 31) * 4;
            float4 xv = *(const float4*)(Xb + (size_t)(k0 + k) * N_PIX + n0 + n4);
            uint4 o = make_uint4(f2tf(xv.x), f2tf(xv.y), f2tf(xv.z), f2tf(xv.w));
            *(uint4*)(Xs + k * 136 + n4) = o;
        }
        __syncthreads();

        #pragma unroll
        for (int kk = 0; kk < 4; kk++) {
            uint32_t a[2][4];
            #pragma unroll
            for (int mt = 0; mt < 2; mt++) {
                int rb = (wr * 32 + mt * 16 + gid) * 36 + kk * 8 + q4;
                a[mt][0] = Ws[rb];
                a[mt][1] = Ws[rb + 8 * 36];
                a[mt][2] = Ws[rb + 4];
                a[mt][3] = Ws[rb + 8 * 36 + 4];
            }
            #pragma unroll
            for (int nt = 0; nt < 4; nt++) {
                int cb = (kk * 8 + q4) * 136 + wc * 32 + nt * 8 + gid;
                uint32_t b[2] = { Xs[cb], Xs[cb + 4 * 136] };
                mma8(acc[0][nt], a[0], b);
                mma8(acc[1][nt], a[1], b);
            }
        }
        __syncthreads();
    }

    #pragma unroll
    for (int mt = 0; mt < 2; mt++) {
        int r0 = m0 + wr * 32 + mt * 16 + gid;
        int r1 = r0 + 8;
        float s0 = gg[r0] * rsqrtf(vv[r0] + EPSB);
        float b0 = bb[r0] - mm[r0] * s0;
        float s1 = gg[r1] * rsqrtf(vv[r1] + EPSB);
        float b1 = bb[r1] - mm[r1] * s1;
        #pragma unroll
        for (int nt = 0; nt < 4; nt++) {
            int n = n0 + wc * 32 + nt * 8 + 2 * q4;
            float2 o0 = make_float2(acc[mt][nt][0] * s0 + b0,
                                    acc[mt][nt][1] * s0 + b0);
            float2 o1 = make_float2(acc[mt][nt][2] * s1 + b1,
                                    acc[mt][nt][3] * s1 + b1);
            *(float2*)(outb + (size_t)r0 * N_PIX + n) = o0;
            *(float2*)(outb + (size_t)r1 * N_PIX + n) = o1;
        }
    }
}

// ---------------------------------------------------------------------------
// Prep: Q,K transpose to [n][d-perm] tf32 (q folds scale*log2e);
//       V cvt to tf32 with j-perm, natural [d][j] layout.
// Grid (128, 8), 256 threads.
// ---------------------------------------------------------------------------
__global__ void __launch_bounds__(256)
prep_qkv(const float* __restrict__ qkv, uint32_t* __restrict__ qt,
         uint32_t* __restrict__ kt, uint32_t* __restrict__ vt)
{
    __shared__ float tq[32][33], tk[32][33];
    const int bh = blockIdx.y;
    const int bbi = bh >> 2, hh = bh & 3;
    const int i0 = blockIdx.x * 32;
    const float* qp = qkv + ((size_t)bbi * HID + hh * 128) * N_PIX;
    const float* kp = qp + 32 * N_PIX;
    const float* vp = qp + 64 * N_PIX;
    const int tid = threadIdx.x;
    #pragma unroll
    for (int r = 0; r < 4; r++) {
        int idx = r * 256 + tid;
        int d = idx >> 5, i = idx & 31;
        tq[d][i] = qp[(size_t)d * N_PIX + i0 + i];
        tk[d][i] = kp[(size_t)d * N_PIX + i0 + i];
    }
    // V: straight cvt+permute (no transpose)
    uint32_t* vtb = vt + (size_t)bh * 64 * N_PIX;
    #pragma unroll
    for (int r = 0; r < 8; r++) {
        int idx = r * 256 + tid;
        int d = idx >> 5, j = idx & 31;
        vtb[(size_t)d * N_PIX + i0 + kperm(j)] =
            f2tf(vp[(size_t)d * N_PIX + i0 + j]);
    }
    __syncthreads();
    const float qscale = 0.17677669529663687f * 1.4426950408889634f; // /sqrt(32)*log2e
    #pragma unroll
    for (int r = 0; r < 4; r++) {
        int idx = r * 256 + tid;
        int i = idx >> 5, d = idx & 31;
        qt[((size_t)bh * N_PIX + i0 + i) * 32 + kperm(d)] = f2tf(tq[d][i] * qscale);
        kt[((size_t)bh * N_PIX + i0 + i) * 32 + kperm(d)] = f2tf(tk[d][i]);
    }
}

// ---------------------------------------------------------------------------
// Attention via mma.sync tf32, fused register-P, vectorized LDS.64 fragments
// (pair-permuted k indices). 256 thr, 2 CTAs/SM.
// SMEM: qs[128][40], ks[128][40], vs[64][136]  (74 KB).
// Pads chosen for conflict-free 64-bit LDS: (4*gid+q4) distinct mod 16
// per half-warp for pad/2 === 4 (mod 16)  ->  40, 136.
// ---------------------------------------------------------------------------
#define QPAD 40
#define VPAD 136
#define QS_OFF 0
#define KS_OFF (128 * QPAD)
#define VS_OFF (2 * 128 * QPAD)
#define ATTN_WORDS (VS_OFF + 64 * VPAD)
#define ATTN_SMEM (ATTN_WORDS * 4)

__global__ void __launch_bounds__(256, 2)
attn_mma(const uint32_t* __restrict__ qt, const uint32_t* __restrict__ kt,
         const uint32_t* __restrict__ vt, float* __restrict__ ybuf)
{
    extern __shared__ uint32_t smu[];
    uint32_t* qs = smu + QS_OFF;
    uint32_t* ks = smu + KS_OFF;
    uint32_t* vs = smu + VS_OFF;

    const int tid = threadIdx.x;
    const int w = tid >> 5, lane = tid & 31;
    const int gid = lane >> 2, q4 = lane & 3;
    const int bh = blockIdx.y;
    const int bbi = bh >> 2, hh = bh & 3;
    const int i0 = blockIdx.x * 128;
    const uint32_t* qtp = qt + ((size_t)bh * N_PIX + i0) * 32;
    const uint32_t* ktp = kt + (size_t)bh * N_PIX * 32;
    const uint32_t* vtp = vt + (size_t)bh * 64 * N_PIX;

    // load Q tile [128][32] -> qs
    #pragma unroll
    for (int r = 0; r < 4; r++) {
        int idx = r * 256 + tid;
        int i = idx >> 3, d4 = (idx & 7) * 4;
        *(uint4*)(qs + i * QPAD + d4) = *(const uint4*)(qtp + (size_t)i * 32 + d4);
    }
    __syncthreads();

    // preload Q fragments (pair-adjacent after perm): warp w owns rows [w*16, w*16+16)
    uint32_t qa[4][4];
    {
        int rb = (w * 16 + gid) * QPAD + 2 * q4;
        #pragma unroll
        for (int kk = 0; kk < 4; kk++) {
            uint2 p0 = *(const uint2*)(qs + rb + kk * 8);            // (d, d+4) row gid
            uint2 p1 = *(const uint2*)(qs + rb + 8 * QPAD + kk * 8); // row gid+8
            qa[kk][0] = p0.x; qa[kk][1] = p1.x;
            qa[kk][2] = p0.y; qa[kk][3] = p1.y;
        }
    }

    const int srcA = (lane & ~3) | (q4 >> 1);
    const int srcB = srcA + 2;
    const bool odd = (q4 & 1) != 0;

    float yacc[8][4] = {};
    float l0 = 0.f, l1 = 0.f;

    for (int jt = 0; jt < 32; jt++) {
        const int j0 = jt * 128;
        __syncthreads();   // prev compute done with ks/vs

        // K tile [128][32] -> ks
        #pragma unroll
        for (int r = 0; r < 4; r++) {
            int idx = r * 256 + tid;
            int j = idx >> 3, d4 = (idx & 7) * 4;
            *(uint4*)(ks + j * QPAD + d4) =
                *(const uint4*)(ktp + (size_t)(j0 + j) * 32 + d4);
        }
        // V tile [64][128] (pre-converted tf32, j-permuted) -> vs
        #pragma unroll
        for (int r = 0; r < 8; r++) {
            int idx = r * 256 + tid;
            int d = idx >> 5, j4 = (idx & 31) * 4;
            *(uint4*)(vs + d * VPAD + j4) =
                *(const uint4*)(vtp + (size_t)d * N_PIX + j0 + j4);
        }
        __syncthreads();

        // fused per j-block: S-mma -> exp2 -> shuffle to A-frag -> PV-mma
        #pragma unroll
        for (int t = 0; t < 16; t++) {
            float s[4] = {0.f, 0.f, 0.f, 0.f};
            int brow = (t * 8 + gid) * QPAD + 2 * q4;
            #pragma unroll
            for (int kk = 0; kk < 4; kk++) {
                uint2 bv = *(const uint2*)(ks + brow + kk * 8);
                uint32_t b[2] = { bv.x, bv.y };
                mma8(s, qa[kk], b);
            }
            // unnormalized exp2 (log2e folded into q) + row sums
            float e0 = exp2f(s[0]), e1 = exp2f(s[1]);
            float e2 = exp2f(s[2]), e3 = exp2f(s[3]);
            l0 += e0 + e1; l1 += e2 + e3;
            uint32_t u0 = f2tf(e0), u1 = f2tf(e1);
            uint32_t u2 = f2tf(e2), u3 = f2tf(e3);
            // C-frag (cols 2q4,2q4+1) -> A-frag (cols q4, q4+4) via quad shfl
            uint32_t f0 = __shfl_sync(0xffffffffu, u0, srcA);
            uint32_t f1 = __shfl_sync(0xffffffffu, u1, srcA);
            uint32_t g0 = __shfl_sync(0xffffffffu, u2, srcA);
            uint32_t g1 = __shfl_sync(0xffffffffu, u3, srcA);
            uint32_t h0 = __shfl_sync(0xffffffffu, u0, srcB);
            uint32_t h1 = __shfl_sync(0xffffffffu, u1, srcB);
            uint32_t k0 = __shfl_sync(0xffffffffu, u2, srcB);
            uint32_t k1 = __shfl_sync(0xffffffffu, u3, srcB);
            uint32_t a[4];
            a[0] = odd ? f1 : f0;   // P[gid][t*8+q4]
            a[1] = odd ? g1 : g0;   // P[gid+8][t*8+q4]
            a[2] = odd ? h1 : h0;   // P[gid][t*8+q4+4]
            a[3] = odd ? k1 : k0;   // P[gid+8][t*8+q4+4]
            // Y += P * V^T for this j-block (k-step = t)
            #pragma unroll
            for (int db = 0; db < 8; db++) {
                uint2 bv = *(const uint2*)(vs + (db * 8 + gid) * VPAD + t * 8 + 2 * q4);
                uint32_t b[2] = { bv.x, bv.y };
                mma8(yacc[db], a, b);
            }
        }
    }

    // reduce row sums across the quad
    l0 += __shfl_xor_sync(0xffffffffu, l0, 1);
    l0 += __shfl_xor_sync(0xffffffffu, l0, 2);
    l1 += __shfl_xor_sync(0xffffffffu, l1, 1);
    l1 += __shfl_xor_sync(0xffffffffu, l1, 2);
    float inv0 = 1.0f / l0, inv1 = 1.0f / l1;

    // normalize + transpose through smem -> coalesced gmem stores
    float* trans = (float*)smu;               // [64][132]
    const int r0 = w * 16 + gid, r1 = r0 + 8;
    __syncthreads();
    #pragma unroll
    for (int t = 0; t < 8; t++) {
        int d0 = t * 8 + 2 * q4;
        trans[(d0 + 0) * 132 + r0] = yacc[t][0] * inv0;
        trans[(d0 + 1) * 132 + r0] = yacc[t][1] * inv0;
        trans[(d0 + 0) * 132 + r1] = yacc[t][2] * inv1;
        trans[(d0 + 1) * 132 + r1] = yacc[t][3] * inv1;
    }
    __syncthreads();
    float* yb = ybuf + ((size_t)bbi * DIMC + hh * 64) * N_PIX + i0;
    #pragma unroll
    for (int r = 0; r < 8; r++) {
        int idx = r * 256 + tid;
        int d = idx >> 5, i4 = (idx & 31) * 4;
        *(float4*)(yb + (size_t)d * N_PIX + i4) = *(float4*)(trans + d * 132 + i4);
    }
}

// ---------------------------------------------------------------------------
// Depthwise 3x3 conv on V + BN, accumulated into ybuf. Channel staged in SMEM.
// ---------------------------------------------------------------------------
__global__ void __launch_bounds__(256)
pe_kernel(const float* __restrict__ qkv, const float* __restrict__ pw,
          const float* __restrict__ gg, const float* __restrict__ bb,
          const float* __restrict__ mm, const float* __restrict__ vv,
          float* __restrict__ ybuf)
{
    __shared__ float ch[4096];
    int bc = blockIdx.x;
    int b = bc >> 8, c = bc & 255;
    const float* vsrc = qkv + ((size_t)b * HID + (c >> 6) * 128 + 64 + (c & 63)) * N_PIX;
    const int tid = threadIdx.x;
    #pragma unroll
    for (int r = 0; r < 4; r++)
        ((float4*)ch)[r * 256 + tid] = ((const float4*)vsrc)[r * 256 + tid];
    float w[9];
    #pragma unroll
    for (int t = 0; t < 9; t++) w[t] = pw[c * 9 + t];
    float s = gg[c] * rsqrtf(vv[c] + EPSB);
    float bias = bb[c] - mm[c] * s;
    float* yp = ybuf + ((size_t)b * DIMC + c) * N_PIX;
    __syncthreads();
    #pragma unroll
    for (int r = 0; r < 16; r++) {
        int p = r * 256 + tid;
        int yy = p >> 6, xx = p & 63;
        float acc = 0.f;
        #pragma unroll
        for (int ky = 0; ky < 3; ky++) {
            int y2 = yy + ky - 1;
            if (y2 < 0 || y2 > 63) continue;
            #pragma unroll
            for (int kx = 0; kx < 3; kx++) {
                int x2 = xx + kx - 1;
                if (x2 < 0 || x2 > 63) continue;
                acc = fmaf(w[ky * 3 + kx], ch[y2 * 64 + x2], acc);
            }
        }
        yp[p] += acc * s + bias;
    }
}

// ---------------------------------------------------------------------------
extern "C" void kernel_launch(void* const* d_in, const int* in_sizes, int n_in,
                              void* d_out, int out_size)
{
    (void)in_sizes; (void)n_in; (void)out_size;
    const float* x      = (const float*)d_in[0];
    const float* qkv_w  = (const float*)d_in[1];
    const float* qkv_g  = (const float*)d_in[2];
    const float* qkv_b  = (const float*)d_in[3];
    const float* qkv_m  = (const float*)d_in[4];
    const float* qkv_v  = (const float*)d_in[5];
    const float* proj_w = (const float*)d_in[6];
    const float* proj_g = (const float*)d_in[7];
    const float* proj_b = (const float*)d_in[8];
    const float* proj_m = (const float*)d_in[9];
    const float* proj_v = (const float*)d_in[10];
    const float* pe_w   = (const float*)d_in[11];
    const float* pe_g   = (const float*)d_in[12];
    const float* pe_b   = (const float*)d_in[13];
    const float* pe_m   = (const float*)d_in[14];
    const float* pe_v   = (const float*)d_in[15];
    float* out = (float*)d_out;

    void *pq = nullptr, *py = nullptr, *pqt = nullptr, *pkt = nullptr, *pvt = nullptr;
    cudaGetSymbolAddress(&pq, g_qkv);
    cudaGetSymbolAddress(&py, g_y);
    cudaGetSymbolAddress(&pqt, g_qt);
    cudaGetSymbolAddress(&pkt, g_kt);
    cudaGetSymbolAddress(&pvt, g_vt);
    float* qkvb = (float*)pq;
    float* yb   = (float*)py;
    uint32_t* qtb = (uint32_t*)pqt;
    uint32_t* ktb = (uint32_t*)pkt;
    uint32_t* vtb = (uint32_t*)pvt;

    cudaFuncSetAttribute(attn_mma, cudaFuncAttributeMaxDynamicSharedMemorySize,
                         ATTN_SMEM);

    // 1) qkv = BN(conv1x1(x))  [tensor cores]
    gemm_tc<<<dim3(32, 8, 2), 256>>>(qkv_w, x, qkv_g, qkv_b, qkv_m, qkv_v, qkvb, HID);
    // 2) prep: q,k -> [n][d-perm] tf32 (scale*log2e folded), v -> tf32 j-perm
    prep_qkv<<<dim3(128, 8), 256>>>(qkvb, qtb, ktb, vtb);
    // 3) attention -> y  (mma.sync tf32, vectorized fragments)
    attn_mma<<<dim3(32, 8), 256, ATTN_SMEM>>>(qtb, ktb, vtb, yb);
    // 4) y += BN(depthwise3x3(v))
    pe_kernel<<<dim3(512), 256>>>(qkvb, pe_w, pe_g, pe_b, pe_m, pe_v, yb);
    // 5) out = BN(conv1x1(y))  [tensor cores]
    gemm_tc<<<dim3(32, 4, 2), 256>>>(proj_w, yb, proj_g, proj_b, proj_m, proj_v, out, DIMC);
}